// round 12
// baseline (speedup 1.0000x reference)
#include <cuda_runtime.h>
#include <math.h>

#define B_SZ 16
#define L_SZ 160000
#define T_FR 999
#define WINS 320
#define HOPS 160
#define NCO  100
#define TM   56
#define NTHREADS 256

#define PI_D 3.14159265358979323846

typedef unsigned long long ull;

// ---------------- quad-interleaved precomputed matrices ----------------
// g_Dwq[(kq*100+c)*4+q] = win[4kq+q] * D[4kq+q][c]      (kq<80)
// g_Eq [(kq*320+w)*4+q] = D[w][4kq+q]                   (kq<25)
// g_Wqi[(kq*100+j)*4+q] = W[j][4kq+q]                   (kq<25)
__device__ __align__(16) float g_Dwq[80 * 100 * 4];
__device__ __align__(16) float g_Eq [25 * 320 * 4];
__device__ __align__(16) float g_Wq1[25 * 100 * 4];
__device__ __align__(16) float g_Wq2[25 * 100 * 4];
__device__ __align__(16) float g_Wq3[25 * 100 * 4];

// ---------------- f32x2 helpers ----------------
__device__ __forceinline__ void fma2(ull& d, ull a, ull b) {
    asm("fma.rn.f32x2 %0, %1, %2, %0;" : "+l"(d) : "l"(a), "l"(b));
}
__device__ __forceinline__ float lanesum(ull v) {
    float lo, hi;
    asm("mov.b64 {%0, %1}, %2;" : "=f"(lo), "=f"(hi) : "l"(v));
    return lo + hi;
}
__device__ __forceinline__ float clip1(float x) {
    return fminf(fmaxf(x, -1.0f), 1.0f);
}

// ---------------- cp.async helpers ----------------
__device__ __forceinline__ void cp16(float* dst_smem, const float* src_gmem) {
    unsigned saddr = (unsigned)__cvta_generic_to_shared(dst_smem);
    asm volatile("cp.async.cg.shared.global [%0], [%1], 16;" :: "r"(saddr), "l"(src_gmem));
}
#define CP_COMMIT() asm volatile("cp.async.commit_group;")
#define CP_WAIT(n)  asm volatile("cp.async.wait_group %0;" :: "n"(n))

template <int NBYTES>
__device__ __forceinline__ void stage_chunk(float* dst, const float* src, int tid) {
    constexpr int NOPS = NBYTES / 16;
    #pragma unroll
    for (int i = 0; i < (NOPS + NTHREADS - 1) / NTHREADS; i++) {
        int idx = tid + i * NTHREADS;
        if (idx < NOPS) cp16(dst + idx * 4, src + idx * 4);
    }
    CP_COMMIT();
}

// ---------------- init kernel: build quad-interleaved matrices ----------------
__global__ void init_mats(const float* __restrict__ W1,
                          const float* __restrict__ W2,
                          const float* __restrict__ W3) {
    int idx = blockIdx.x * blockDim.x + threadIdx.x;
    if (idx < 80 * 100 * 4) {   // Dwq
        int q  = idx & 3;
        int c  = (idx >> 2) % 100;
        int kq = idx / 400;
        int k  = 4 * kq + q;    // sample index 0..319
        double d = sqrt(2.0 / (double)WINS) * cos((k + 0.5) * PI_D / (double)WINS * (double)c);
        if (c == 0) d *= sqrt(0.5);
        double win = 0.5 * (1.0 - cos(2.0 * PI_D * (double)k / (double)WINS));
        g_Dwq[idx] = (float)(win * d);
    }
    if (idx < 25 * 320 * 4) {   // Eq
        int q  = idx & 3;
        int w  = (idx >> 2) % 320;
        int kq = idx / 1280;
        int c  = 4 * kq + q;    // coefficient index 0..99
        double d = sqrt(2.0 / (double)WINS) * cos((w + 0.5) * PI_D / (double)WINS * (double)c);
        if (c == 0) d *= sqrt(0.5);
        g_Eq[idx] = (float)d;
    }
    if (idx < 25 * 100 * 4) {   // Wq1/2/3
        int q  = idx & 3;
        int j  = (idx >> 2) % 100;
        int kq = idx / 400;
        int k  = 4 * kq + q;    // input-feature index 0..99
        g_Wq1[idx] = W1[j * NCO + k];
        g_Wq2[idx] = W2[j * NCO + k];
        g_Wq3[idx] = W3[j * NCO + k];
    }
}

// smem: sig[9120] | bufA[5824] | bufB[5824] | wbuf[2*2000]  = 99,072 B
#define SIG_LEN  ((TM - 1) * HOPS + WINS)   // 9120
#define RM_STR   104                         // row stride (16B-aligned rows)
#define BUF_SZ   (TM * RM_STR)               // 5824
#define WBUF_STR 2000                        // 5 kq * 100 cols * 4 floats
#define SMEM_FLOATS (SIG_LEN + 2 * BUF_SZ + 2 * WBUF_STR)
#define SMEM_BYTES  (SMEM_FLOATS * 4)

// ---- stage-1 DCT: K=320 = 16 chunks x 5 kq, weights staged via cp.async ----
// DST_SMEM: write bufA row-major; else write global only.
template <bool DST_SMEM>
__device__ __forceinline__ void dct_pass(
    const float* __restrict__ sig, float* __restrict__ bufA, float* __restrict__ wbuf,
    float* __restrict__ gdst, int b, int t0, int tid, int tx, int ty)
{
    const bool pred4 = (tx < 4);
    ull acc[7][4] = {};
    stage_chunk<8000>(wbuf, g_Dwq, tid);
    for (int c = 0; c < 16; c++) {
        if (c < 15) { stage_chunk<8000>(wbuf + ((c + 1) & 1) * WBUF_STR, g_Dwq + (c + 1) * 2000, tid); CP_WAIT(1); }
        else        { CP_WAIT(0); }
        __syncthreads();
        const ulonglong2* __restrict__ W = reinterpret_cast<const ulonglong2*>(wbuf + (c & 1) * WBUF_STR);
        #pragma unroll 2
        for (int kl = 0; kl < 5; kl++) {
            const ulonglong2* wr = W + kl * 100;
            ulonglong2 w0 = wr[tx];
            ulonglong2 w1 = wr[32 + tx];
            ulonglong2 w2 = wr[64 + tx];
            ulonglong2 w3 = pred4 ? wr[96 + tx] : make_ulonglong2(0ull, 0ull);
            const int ko = (c * 5 + kl) * 4;
            #pragma unroll
            for (int i = 0; i < 7; i++) {
                ulonglong2 a = *reinterpret_cast<const ulonglong2*>(&sig[(ty + 8 * i) * HOPS + ko]);
                fma2(acc[i][0], a.x, w0.x); fma2(acc[i][0], a.y, w0.y);
                fma2(acc[i][1], a.x, w1.x); fma2(acc[i][1], a.y, w1.y);
                fma2(acc[i][2], a.x, w2.x); fma2(acc[i][2], a.y, w2.y);
                fma2(acc[i][3], a.x, w3.x); fma2(acc[i][3], a.y, w3.y);
            }
        }
        __syncthreads();
    }
    #pragma unroll
    for (int i = 0; i < 7; i++) {
        const int r = ty + 8 * i;
        const int t = t0 + r;
        #pragma unroll
        for (int jb = 0; jb < 4; jb++) {
            const int j = tx + 32 * jb;
            const bool jv = (jb < 3) || pred4;
            float val = clip1(lanesum(acc[i][jb]));
            if (DST_SMEM) {
                if (jv) bufA[r * RM_STR + j] = val;
            } else if (jv && t < T_FR) {
                gdst[((size_t)b * T_FR + t) * NCO + j] = val;
            }
        }
    }
}

// ---- MLP stage: K=100 = 5 chunks x 5 kq, staged. ACT: 0 prelu, 1 tanh. ----
template <int ACT, bool WRITE_G>
__device__ __forceinline__ void mlp_stage(
    const float* __restrict__ Asm, float* __restrict__ Bsm, float* __restrict__ wbuf,
    const float* __restrict__ Wqg, const float* __restrict__ bias, float alpha,
    int tid, int tx, int ty, float* __restrict__ gout, int b, int t0)
{
    const bool pred4 = (tx < 4);
    ull acc[7][4] = {};
    stage_chunk<8000>(wbuf, Wqg, tid);
    for (int c = 0; c < 5; c++) {
        if (c < 4) { stage_chunk<8000>(wbuf + ((c + 1) & 1) * WBUF_STR, Wqg + (c + 1) * 2000, tid); CP_WAIT(1); }
        else       { CP_WAIT(0); }
        __syncthreads();
        const ulonglong2* __restrict__ W = reinterpret_cast<const ulonglong2*>(wbuf + (c & 1) * WBUF_STR);
        #pragma unroll 2
        for (int kl = 0; kl < 5; kl++) {
            const ulonglong2* wr = W + kl * 100;
            ulonglong2 w0 = wr[tx];
            ulonglong2 w1 = wr[32 + tx];
            ulonglong2 w2 = wr[64 + tx];
            ulonglong2 w3 = pred4 ? wr[96 + tx] : make_ulonglong2(0ull, 0ull);
            const int ko = (c * 5 + kl) * 4;
            #pragma unroll
            for (int i = 0; i < 7; i++) {
                ulonglong2 a = *reinterpret_cast<const ulonglong2*>(&Asm[(ty + 8 * i) * RM_STR + ko]);
                fma2(acc[i][0], a.x, w0.x); fma2(acc[i][0], a.y, w0.y);
                fma2(acc[i][1], a.x, w1.x); fma2(acc[i][1], a.y, w1.y);
                fma2(acc[i][2], a.x, w2.x); fma2(acc[i][2], a.y, w2.y);
                fma2(acc[i][3], a.x, w3.x); fma2(acc[i][3], a.y, w3.y);
            }
        }
        __syncthreads();
    }
    float bj[4];
    bj[0] = bias[tx];
    bj[1] = bias[32 + tx];
    bj[2] = bias[64 + tx];
    bj[3] = pred4 ? bias[96 + tx] : 0.f;
    #pragma unroll
    for (int i = 0; i < 7; i++) {
        const int r = ty + 8 * i;
        const int t = t0 + r;
        #pragma unroll
        for (int jb = 0; jb < 4; jb++) {
            const int j = tx + 32 * jb;
            const bool jv = (jb < 3) || pred4;
            float val = lanesum(acc[i][jb]) + bj[jb];
            if (ACT == 0) val = (val >= 0.f) ? val : alpha * val;
            else          val = tanhf(val);
            if (jv) Bsm[r * RM_STR + j] = val;
            if (WRITE_G && jv && t < T_FR)
                gout[((size_t)b * T_FR + t) * NCO + j] = val;
        }
    }
}

__device__ __forceinline__ void load_seg(const float* __restrict__ g, float* __restrict__ s,
                                         int seglen, int tid) {
    const float4* g4 = reinterpret_cast<const float4*>(g);
    float4* s4 = reinterpret_cast<float4*>(s);
    const int segv = seglen >> 2;
    const float4 z4 = make_float4(0.f, 0.f, 0.f, 0.f);
    for (int i = tid; i < (SIG_LEN >> 2); i += NTHREADS)
        s4[i] = (i < segv) ? g4[i] : z4;
}

__global__ __launch_bounds__(NTHREADS, 2) void fused_kernel(
    const float* __restrict__ noisy, const float* __restrict__ clean,
    const float* __restrict__ b1, const float* __restrict__ p1g,
    const float* __restrict__ b2, const float* __restrict__ p2g,
    const float* __restrict__ b3,
    float* __restrict__ out_dct, float* __restrict__ cln_dct,
    float* __restrict__ out_sp)
{
    extern __shared__ float smem[];
    float* sig  = smem;
    float* bufA = smem + SIG_LEN;
    float* bufB = bufA + BUF_SZ;
    float* wbuf = bufB + BUF_SZ;

    const int tid = threadIdx.x;
    const int tx  = tid & 31;
    const int ty  = tid >> 5;          // warp 0..7; rows ty+8i, i=0..6
    const int b   = blockIdx.y;
    const int t0  = blockIdx.x * TM;
    const int nf  = min(TM, T_FR - t0);
    const int seglen = (nf - 1) * HOPS + WINS;

    const float alpha1 = p1g[0];
    const float alpha2 = p2g[0];

    // ---- clean: DCT -> global ----
    load_seg(clean + (size_t)b * L_SZ + (size_t)t0 * HOPS, sig, seglen, tid);
    __syncthreads();
    dct_pass<false>(sig, bufA, wbuf, cln_dct, b, t0, tid, tx, ty);
    __syncthreads();

    // ---- noisy: DCT -> bufA ----
    load_seg(noisy + (size_t)b * L_SZ + (size_t)t0 * HOPS, sig, seglen, tid);
    __syncthreads();
    dct_pass<true>(sig, bufA, wbuf, nullptr, b, t0, tid, tx, ty);
    __syncthreads();

    // ---- MLP ----
    mlp_stage<0, false>(bufA, bufB, wbuf, g_Wq1, b1, alpha1, tid, tx, ty, nullptr, b, t0);
    __syncthreads();
    mlp_stage<0, false>(bufB, bufA, wbuf, g_Wq2, b2, alpha2, tid, tx, ty, nullptr, b, t0);
    __syncthreads();
    mlp_stage<1, true >(bufA, bufB, wbuf, g_Wq3, b3, 0.f,    tid, tx, ty, out_dct, b, t0);
    __syncthreads();

    // ---- IDCT: K=100 (25 k-quads), weights direct from L2, two column halves ----
    const ulonglong2* __restrict__ Eq = reinterpret_cast<const ulonglong2*>(g_Eq);
    #pragma unroll 1
    for (int h = 0; h < 2; h++) {
        ull acc[7][5] = {};
        #pragma unroll 1
        for (int kq = 0; kq < 25; kq++) {
            const ulonglong2* er = Eq + kq * 320;
            ulonglong2 w[5];
            #pragma unroll
            for (int jj = 0; jj < 5; jj++) w[jj] = er[tx + 32 * (5 * h + jj)];
            const int ko = kq * 4;
            #pragma unroll
            for (int i = 0; i < 7; i++) {
                ulonglong2 a = *reinterpret_cast<const ulonglong2*>(&bufB[(ty + 8 * i) * RM_STR + ko]);
                #pragma unroll
                for (int jj = 0; jj < 5; jj++) {
                    fma2(acc[i][jj], a.x, w[jj].x);
                    fma2(acc[i][jj], a.y, w[jj].y);
                }
            }
        }
        #pragma unroll
        for (int i = 0; i < 7; i++) {
            const int t = t0 + ty + 8 * i;
            if (t < T_FR) {
                float* dst = out_sp + (size_t)b * L_SZ + (size_t)t * HOPS;
                #pragma unroll
                for (int jj = 0; jj < 5; jj++)
                    atomicAdd(&dst[tx + 32 * (5 * h + jj)], lanesum(acc[i][jj]));
            }
        }
    }
}

// ---------------- launch ----------------
extern "C" void kernel_launch(void* const* d_in, const int* in_sizes, int n_in,
                              void* d_out, int out_size) {
    const float* noisy = (const float*)d_in[0];
    const float* clean = (const float*)d_in[1];
    const float* W1    = (const float*)d_in[2];
    const float* b1    = (const float*)d_in[3];
    const float* p1    = (const float*)d_in[4];
    const float* W2    = (const float*)d_in[5];
    const float* b2    = (const float*)d_in[6];
    const float* p2    = (const float*)d_in[7];
    const float* W3    = (const float*)d_in[8];
    const float* b3    = (const float*)d_in[9];

    float* out      = (float*)d_out;
    float* out_dct  = out;                                   // [16, 999, 100]
    float* cln_dct  = out + (size_t)B_SZ * T_FR * NCO;       // [16, 999, 100]
    float* out_sp   = out + 2 * (size_t)B_SZ * T_FR * NCO;   // [16, 160000]

    cudaMemsetAsync(out_sp, 0, (size_t)B_SZ * L_SZ * sizeof(float), 0);

    init_mats<<<(80 * 100 * 4 + 255) / 256, 256>>>(W1, W2, W3);

    cudaFuncSetAttribute(fused_kernel, cudaFuncAttributeMaxDynamicSharedMemorySize, SMEM_BYTES);
    dim3 grid((T_FR + TM - 1) / TM, B_SZ);
    fused_kernel<<<grid, NTHREADS, SMEM_BYTES>>>(noisy, clean, b1, p1, b2, p2, b3,
                                                 out_dct, cln_dct, out_sp);
}